// round 7
// baseline (speedup 1.0000x reference)
#include <cuda_runtime.h>

// Collapsed SimpleAttention: out[b,k] = (mean_s x[b,s,:]) @ Wv[:,k] + bv[k]
// (softmax over the query axis => sum_q att[b,q,s] = 1 => Q/K/att cancel
//  exactly under the mean-pool).
//
// SINGLE fused kernel, SINGLE grid barrier.
// Stage 1 (592 blocks): column partial sums of x.
// Barrier (arrive=atomicAdd, wait=volatile-load poll).
// Stage 2 (64 blocks = ktile x b): re-reduce partials -> xbar (smem, redundant
// per ktile — cheaper than two more grid barriers), then 64k x 1024d GEMM
// slice + bias -> d_out directly. No intermediate stages, no extra barriers.

#define BB     8
#define SS     2048
#define DD     1024
#define DKK    512
#define NCHUNK 74                       // stage-1 blocks per batch
#define TOTB   (NCHUNK * BB)            // 592

__device__ float g_partial[BB * NCHUNK * DD];   // [b][chunk][d]
__device__ unsigned g_c1 = 0, g_done = 0;

__device__ __forceinline__ void spin_until(unsigned* ctr, unsigned target) {
    const volatile unsigned* p = (const volatile unsigned*)ctr;
    while (*p != target) __nanosleep(32);
}

__global__ void __launch_bounds__(256, 4)
fused_kernel(const float* __restrict__ x,
             const float* __restrict__ Wv,
             const float* __restrict__ bv,
             float* __restrict__ out) {
    __shared__ float xbs[DD];           // xbar for this block's batch
    __shared__ float red[4][64];        // GEMM quarter-reduce

    const int j = blockIdx.x;           // 0..73
    const int b = blockIdx.y;           // 0..7
    const int t = threadIdx.x;

    // ======================= Stage 1: column sum of x ======================
    {
        const int d  = t * 4;
        const int r0 = (j * SS) / NCHUNK;
        const int r1 = ((j + 1) * SS) / NCHUNK;
        const int n  = r1 - r0;

        const float4* xp = reinterpret_cast<const float4*>(
            x + ((size_t)(b * SS + r0)) * DD + d);
        const size_t rs = DD / 4;

        float4 a0 = make_float4(0.f, 0.f, 0.f, 0.f);
        float4 a1 = make_float4(0.f, 0.f, 0.f, 0.f);
        float4 a2 = make_float4(0.f, 0.f, 0.f, 0.f);
        float4 a3 = make_float4(0.f, 0.f, 0.f, 0.f);

        int s = 0;
        for (; s + 8 <= n; s += 8, xp += 8 * rs) {
            const float4 v0 = xp[0 * rs];
            const float4 v1 = xp[1 * rs];
            const float4 v2 = xp[2 * rs];
            const float4 v3 = xp[3 * rs];
            const float4 v4 = xp[4 * rs];
            const float4 v5 = xp[5 * rs];
            const float4 v6 = xp[6 * rs];
            const float4 v7 = xp[7 * rs];
            a0.x += v0.x; a0.y += v0.y; a0.z += v0.z; a0.w += v0.w;
            a1.x += v1.x; a1.y += v1.y; a1.z += v1.z; a1.w += v1.w;
            a2.x += v2.x; a2.y += v2.y; a2.z += v2.z; a2.w += v2.w;
            a3.x += v3.x; a3.y += v3.y; a3.z += v3.z; a3.w += v3.w;
            a0.x += v4.x; a0.y += v4.y; a0.z += v4.z; a0.w += v4.w;
            a1.x += v5.x; a1.y += v5.y; a1.z += v5.z; a1.w += v5.w;
            a2.x += v6.x; a2.y += v6.y; a2.z += v6.z; a2.w += v6.w;
            a3.x += v7.x; a3.y += v7.y; a3.z += v7.z; a3.w += v7.w;
        }
        for (; s < n; s++, xp += rs) {
            const float4 v = *xp;
            a0.x += v.x; a0.y += v.y; a0.z += v.z; a0.w += v.w;
        }
        a0.x += a1.x; a0.y += a1.y; a0.z += a1.z; a0.w += a1.w;
        a2.x += a3.x; a2.y += a3.y; a2.z += a3.z; a2.w += a3.w;
        a0.x += a2.x; a0.y += a2.y; a0.z += a2.z; a0.w += a2.w;

        *reinterpret_cast<float4*>(
            g_partial + ((size_t)(b * NCHUNK + j)) * DD + d) = a0;
    }
    __syncthreads();
    __threadfence();                    // release partials
    if (t == 0) atomicAdd(&g_c1, 1u);

    if (j >= 8) return;                 // 528 blocks done; 64 continue

    // ==================== Barrier: all 592 partials ready ==================
    if (t == 0) spin_until(&g_c1, TOTB);
    __syncthreads();
    __threadfence();                    // acquire

    // ====== Stage 2: xbar (redundant per ktile) + GEMM slice -> d_out ======
    const int ktile = j;                // 0..7 -> k range [64*ktile, 64*ktile+64)
    const int kbase = ktile * 64;

    // Phase A: xbar[b][d] for all 1024 d. Thread t owns float4 at d=4t.
    {
        const float4* p = reinterpret_cast<const float4*>(
            g_partial + (size_t)(b * NCHUNK) * DD) + t;
        float4 a = make_float4(0.f, 0.f, 0.f, 0.f);
#pragma unroll 4
        for (int c = 0; c < NCHUNK; c++) {
            const float4 v = p[(size_t)c * (DD / 4)];
            a.x += v.x; a.y += v.y; a.z += v.z; a.w += v.w;
        }
        const float inv = 1.0f / (float)SS;
        a.x *= inv; a.y *= inv; a.z *= inv; a.w *= inv;
        reinterpret_cast<float4*>(xbs)[t] = a;
    }
    __syncthreads();

    // Phase B: thread owns k = kbase + (t&63), d-quarter q = t>>6 (256 d).
    // Warp Wv reads: 32 consecutive k = 128B coalesced.
    {
        const int kk = t & 63;
        const int q  = t >> 6;
        const int d0 = q * 256;
        const float* wp = Wv + (size_t)d0 * DKK + kbase + kk;
        float a = 0.f;
#pragma unroll 8
        for (int d = 0; d < 256; d++)
            a += xbs[d0 + d] * wp[(size_t)d * DKK];
        red[q][kk] = a;
    }
    __syncthreads();

    if (t < 64) {
        const float s = red[0][t] + red[1][t] + red[2][t] + red[3][t]
                        + bv[kbase + t];
        out[(size_t)b * DKK + kbase + t] = s;
    }

    // ================= Counter reset (last stage-2 block) ==================
    __syncthreads();
    if (t == 0) {
        const unsigned old = atomicAdd(&g_done, 1u);
        if (old == 63u) {               // all 64 stage-2 blocks finished
            g_c1 = 0; g_done = 0;
            __threadfence();
        }
    }
}

// ---------------------------------------------------------------------------
// Inputs (metadata order): x, Wq, bq, Wk, bk, Wv, bv
// ---------------------------------------------------------------------------
extern "C" void kernel_launch(void* const* d_in, const int* in_sizes, int n_in,
                              void* d_out, int out_size) {
    const float* x  = (const float*)d_in[0];
    const float* Wv = (const float*)d_in[5];
    const float* bv = (const float*)d_in[6];
    float* out = (float*)d_out;

    fused_kernel<<<dim3(NCHUNK, BB), 256>>>(x, Wv, bv, out);
}

// round 8
// speedup vs baseline: 1.3249x; 1.3249x over previous
#include <cuda_runtime.h>

// Collapsed SimpleAttention: out[b,k] = (mean_s x[b,s,:]) @ Wv[:,k] + bv[k]
// (softmax over the query axis => sum_q att[b,q,s] = 1 => Q/K/att cancel
//  exactly under the mean-pool).
//
// SINGLE kernel, NO grid-wide barrier. Per-batch dataflow:
//   stage 1 (592 blocks): column partial sums; arrive on per-batch counter.
//   stage 2 (64 blocks = 8 ktile x 8 b): wait ONLY for own batch's 74
//     partials, redundantly reduce xbar[b] in smem (8-way parallel per batch),
//     then GEMM slice with 32 independent register-batched Wv loads per group
//     (high MLP — the R6 tail regression was serialized strided loads),
//     + bias -> d_out. Early batches' tails overlap late stage-1 blocks.
// Deterministic: fixed partitioning, no float atomics. Counters reset by the
// last finishing consumer block => graph-replayable.

#define BB     8
#define SS     2048
#define DD     1024
#define DKK    512
#define NCHUNK 74                       // stage-1 blocks per batch
#define TOTB   (NCHUNK * BB)            // 592 = 4 * 148 (one balanced wave)

__device__ float g_partial[BB * NCHUNK * DD];   // [b][chunk][d]
__device__ unsigned g_cb[BB] = {0};             // per-batch arrival counters
__device__ unsigned g_done = 0;

__device__ __forceinline__ void spin_until(unsigned* ctr, unsigned target) {
    const volatile unsigned* p = (const volatile unsigned*)ctr;
    while (*p != target) __nanosleep(32);
}

__global__ void __launch_bounds__(256, 4)
fused_kernel(const float* __restrict__ x,
             const float* __restrict__ Wv,
             const float* __restrict__ bv,
             float* __restrict__ out) {
    __shared__ float xbs[DD];           // xbar for this block's batch
    __shared__ float red[4][64];        // GEMM quarter-reduce

    const int j = blockIdx.x;           // 0..73
    const int b = blockIdx.y;           // 0..7
    const int t = threadIdx.x;

    // ======================= Stage 1: column sum of x ======================
    {
        const int d  = t * 4;
        const int r0 = (j * SS) / NCHUNK;
        const int r1 = ((j + 1) * SS) / NCHUNK;
        const int n  = r1 - r0;

        const float4* xp = reinterpret_cast<const float4*>(
            x + ((size_t)(b * SS + r0)) * DD + d);
        const size_t rs = DD / 4;

        float4 a0 = make_float4(0.f, 0.f, 0.f, 0.f);
        float4 a1 = make_float4(0.f, 0.f, 0.f, 0.f);
        float4 a2 = make_float4(0.f, 0.f, 0.f, 0.f);
        float4 a3 = make_float4(0.f, 0.f, 0.f, 0.f);

        int s = 0;
        for (; s + 8 <= n; s += 8, xp += 8 * rs) {
            const float4 v0 = xp[0 * rs];
            const float4 v1 = xp[1 * rs];
            const float4 v2 = xp[2 * rs];
            const float4 v3 = xp[3 * rs];
            const float4 v4 = xp[4 * rs];
            const float4 v5 = xp[5 * rs];
            const float4 v6 = xp[6 * rs];
            const float4 v7 = xp[7 * rs];
            a0.x += v0.x; a0.y += v0.y; a0.z += v0.z; a0.w += v0.w;
            a1.x += v1.x; a1.y += v1.y; a1.z += v1.z; a1.w += v1.w;
            a2.x += v2.x; a2.y += v2.y; a2.z += v2.z; a2.w += v2.w;
            a3.x += v3.x; a3.y += v3.y; a3.z += v3.z; a3.w += v3.w;
            a0.x += v4.x; a0.y += v4.y; a0.z += v4.z; a0.w += v4.w;
            a1.x += v5.x; a1.y += v5.y; a1.z += v5.z; a1.w += v5.w;
            a2.x += v6.x; a2.y += v6.y; a2.z += v6.z; a2.w += v6.w;
            a3.x += v7.x; a3.y += v7.y; a3.z += v7.z; a3.w += v7.w;
        }
        for (; s < n; s++, xp += rs) {
            const float4 v = *xp;
            a0.x += v.x; a0.y += v.y; a0.z += v.z; a0.w += v.w;
        }
        a0.x += a1.x; a0.y += a1.y; a0.z += a1.z; a0.w += a1.w;
        a2.x += a3.x; a2.y += a3.y; a2.z += a3.z; a2.w += a3.w;
        a0.x += a2.x; a0.y += a2.y; a0.z += a2.z; a0.w += a2.w;

        *reinterpret_cast<float4*>(
            g_partial + ((size_t)(b * NCHUNK + j)) * DD + d) = a0;
    }
    __syncthreads();
    __threadfence();                    // release partials
    if (t == 0) atomicAdd(&g_cb[b], 1u);

    if (j >= 8) return;                 // 528 blocks done; 64 continue

    // =============== Wait for THIS batch's 74 partials only ================
    if (t == 0) spin_until(&g_cb[b], NCHUNK);
    __syncthreads();
    __threadfence();                    // acquire

    const int ktile = j;                // k range [64*ktile, 64*ktile+64)
    const int kbase = ktile * 64;

    // ========= Phase A: xbar[b][d] redundant reduce into smem ==============
    {
        const float4* p = reinterpret_cast<const float4*>(
            g_partial + (size_t)(b * NCHUNK) * DD) + t;
        const size_t cs = DD / 4;

        float4 a0 = make_float4(0.f, 0.f, 0.f, 0.f);
        float4 a1 = make_float4(0.f, 0.f, 0.f, 0.f);
        float4 a2 = make_float4(0.f, 0.f, 0.f, 0.f);
        float4 a3 = make_float4(0.f, 0.f, 0.f, 0.f);
        int c = 0;
        for (; c + 8 <= NCHUNK; c += 8) {
            const float4 v0 = p[(size_t)(c + 0) * cs];
            const float4 v1 = p[(size_t)(c + 1) * cs];
            const float4 v2 = p[(size_t)(c + 2) * cs];
            const float4 v3 = p[(size_t)(c + 3) * cs];
            const float4 v4 = p[(size_t)(c + 4) * cs];
            const float4 v5 = p[(size_t)(c + 5) * cs];
            const float4 v6 = p[(size_t)(c + 6) * cs];
            const float4 v7 = p[(size_t)(c + 7) * cs];
            a0.x += v0.x; a0.y += v0.y; a0.z += v0.z; a0.w += v0.w;
            a1.x += v1.x; a1.y += v1.y; a1.z += v1.z; a1.w += v1.w;
            a2.x += v2.x; a2.y += v2.y; a2.z += v2.z; a2.w += v2.w;
            a3.x += v3.x; a3.y += v3.y; a3.z += v3.z; a3.w += v3.w;
            a0.x += v4.x; a0.y += v4.y; a0.z += v4.z; a0.w += v4.w;
            a1.x += v5.x; a1.y += v5.y; a1.z += v5.z; a1.w += v5.w;
            a2.x += v6.x; a2.y += v6.y; a2.z += v6.z; a2.w += v6.w;
            a3.x += v7.x; a3.y += v7.y; a3.z += v7.z; a3.w += v7.w;
        }
        for (; c < NCHUNK; c++) {
            const float4 v = p[(size_t)c * cs];
            a0.x += v.x; a0.y += v.y; a0.z += v.z; a0.w += v.w;
        }
        a0.x += a1.x; a0.y += a1.y; a0.z += a1.z; a0.w += a1.w;
        a2.x += a3.x; a2.y += a3.y; a2.z += a3.z; a2.w += a3.w;
        a0.x += a2.x; a0.y += a2.y; a0.z += a2.z; a0.w += a2.w;

        const float inv = 1.0f / (float)SS;
        a0.x *= inv; a0.y *= inv; a0.z *= inv; a0.w *= inv;
        reinterpret_cast<float4*>(xbs)[t] = a0;
    }
    __syncthreads();

    // ===== Phase B: GEMM slice, 32 independent Wv loads per group ==========
    {
        const int kk = t & 63;
        const int q  = t >> 6;
        const int d0 = q * 256;
        float acc = 0.f;
#pragma unroll
        for (int g = 0; g < 8; g++) {
            const int dg = d0 + g * 32;
            float w[32];
#pragma unroll
            for (int i = 0; i < 32; i++)
                w[i] = Wv[(size_t)(dg + i) * DKK + kbase + kk];
#pragma unroll
            for (int i = 0; i < 32; i++)
                acc += w[i] * xbs[dg + i];
        }
        red[q][kk] = acc;
    }
    __syncthreads();

    if (t < 64) {
        out[(size_t)b * DKK + kbase + t] =
            red[0][t] + red[1][t] + red[2][t] + red[3][t] + bv[kbase + t];
    }

    // ================= Counter reset (last consumer block) =================
    __syncthreads();
    if (t == 0) {
        const unsigned old = atomicAdd(&g_done, 1u);
        if (old == 63u) {               // all 64 consumer blocks finished
#pragma unroll
            for (int i = 0; i < BB; i++) g_cb[i] = 0;
            g_done = 0;
            __threadfence();
        }
    }
}

// ---------------------------------------------------------------------------
// Inputs (metadata order): x, Wq, bq, Wk, bk, Wv, bv
// ---------------------------------------------------------------------------
extern "C" void kernel_launch(void* const* d_in, const int* in_sizes, int n_in,
                              void* d_out, int out_size) {
    const float* x  = (const float*)d_in[0];
    const float* Wv = (const float*)d_in[5];
    const float* bv = (const float*)d_in[6];
    float* out = (float*)d_out;

    fused_kernel<<<dim3(NCHUNK, BB), 256>>>(x, Wv, bv, out);
}